// round 11
// baseline (speedup 1.0000x reference)
#include <cuda_runtime.h>
#include <math.h>

#define B_   32
#define KV_  4096
#define H_   4096
#define NH_  32
#define NKV_ 8
#define D_   128
#define G_   4
#define QKVN ((NH_ + 2*NKV_) * D_)   // 6144
#define SCALE_ 0.08838834764831845f  // 128^-0.5
#define SPLITK 16
#define NCHUNK 16
#define CS     (KV_ / NCHUNK)        // 256 slots per chunk

// ---- scratch (device globals: no allocation) ----
__device__ float  g_qkv[B_ * QKVN];
__device__ float  g_part[SPLITK * B_ * QKVN];            // 12.6 MB
__device__ float  g_opart[NCHUNK * B_ * NKV_ * G_ * D_];
__device__ float  g_ms[NCHUNK * B_ * NKV_ * G_ * 2];
__device__ float  g_o[B_ * NH_ * D_];
__device__ double g_invf[64];
__device__ float  g_cosb[B_][64];
__device__ float  g_sinb[B_][64];

// ---- tiny prelaunch kernels (keep gemm in profiler slot 4) ----
__global__ void rope_invf_kernel() {
    int i = threadIdx.x;
    if (i < 64) g_invf[i] = pow(1.0e6, -(double)i / 64.0);
}
__global__ void rope_cos_kernel(const int* __restrict__ position_ids) {
    int b = blockIdx.x, i = threadIdx.x;
    g_cosb[b][i] = (float)cos((double)position_ids[b] * g_invf[i]);
}
__global__ void rope_sin_kernel(const int* __restrict__ position_ids) {
    int b = blockIdx.x, i = threadIdx.x;
    g_sinb[b][i] = (float)sin((double)position_ids[b] * g_invf[i]);
}

// ============================================================
// Split-K GEMM (fp32 FFMA), register-prefetch double buffering.
// SPLITK=16 -> 768/512 blocks: 5.2/3.5 CTAs per SM to hide
// barrier + memory latency (R10 profile: occ 30%, nothing saturated).
// ============================================================
__global__ __launch_bounds__(256) void gemm_splitk(
        const float* __restrict__ A, const float* __restrict__ W,
        float* __restrict__ P, int N, int K) {
    __shared__ float As[32][36];
    __shared__ float Ws[32][132];
    const int tid = threadIdx.x;
    const int tx = tid & 31;
    const int ty = tid >> 5;
    const int n0 = blockIdx.x * 128;
    const int kslice = K / SPLITK;
    const int kbase = blockIdx.y * kslice;

    const int m_a = tid >> 3, c_a = (tid & 7) * 4;
    const float* Aptr = &A[m_a * K + kbase + c_a];
    const float* Wptr[4];
    int n_w[4], c_w[4];
    #pragma unroll
    for (int j = 0; j < 4; j++) {
        int f = tid + j * 256;
        n_w[j] = f >> 3; c_w[j] = (f & 7) * 4;
        Wptr[j] = &W[(size_t)(n0 + n_w[j]) * K + kbase + c_w[j]];
    }

    float acc[4][4];
    #pragma unroll
    for (int i = 0; i < 4; i++)
        #pragma unroll
        for (int j = 0; j < 4; j++) acc[i][j] = 0.f;

    float4 a_reg = *(const float4*)Aptr;
    float4 w_reg[4];
    #pragma unroll
    for (int j = 0; j < 4; j++) w_reg[j] = *(const float4*)Wptr[j];

    const int nchunks = kslice / 32;
    for (int ck = 0; ck < nchunks; ck++) {
        As[c_a + 0][m_a] = a_reg.x; As[c_a + 1][m_a] = a_reg.y;
        As[c_a + 2][m_a] = a_reg.z; As[c_a + 3][m_a] = a_reg.w;
        #pragma unroll
        for (int j = 0; j < 4; j++) {
            Ws[c_w[j] + 0][n_w[j]] = w_reg[j].x;
            Ws[c_w[j] + 1][n_w[j]] = w_reg[j].y;
            Ws[c_w[j] + 2][n_w[j]] = w_reg[j].z;
            Ws[c_w[j] + 3][n_w[j]] = w_reg[j].w;
        }
        __syncthreads();

        if (ck + 1 < nchunks) {
            a_reg = *(const float4*)(Aptr + (ck + 1) * 32);
            #pragma unroll
            for (int j = 0; j < 4; j++)
                w_reg[j] = *(const float4*)(Wptr[j] + (ck + 1) * 32);
        }

        #pragma unroll
        for (int kk = 0; kk < 32; kk++) {
            float4 a4 = *(const float4*)&As[kk][ty * 4];
            float4 b4 = *(const float4*)&Ws[kk][tx * 4];
            float av[4] = {a4.x, a4.y, a4.z, a4.w};
            float bv[4] = {b4.x, b4.y, b4.z, b4.w};
            #pragma unroll
            for (int i = 0; i < 4; i++)
                #pragma unroll
                for (int j = 0; j < 4; j++) acc[i][j] += av[i] * bv[j];
        }
        __syncthreads();
    }
    float* p = P + (size_t)blockIdx.y * 32 * N;
    #pragma unroll
    for (int i = 0; i < 4; i++)
        *(float4*)&p[(ty * 4 + i) * N + n0 + tx * 4] =
            make_float4(acc[i][0], acc[i][1], acc[i][2], acc[i][3]);
}

// reduce split-K partials for the O projection into d_out
__global__ void reduce_out(float* __restrict__ out, int total4) {
    int i = blockIdx.x * blockDim.x + threadIdx.x;
    if (i >= total4) return;
    float4 r = make_float4(0.f, 0.f, 0.f, 0.f);
    #pragma unroll
    for (int s = 0; s < SPLITK; s++) {
        float4 x = *(const float4*)&g_part[(size_t)s * (B_ * H_) + i * 4];
        r.x += x.x; r.y += x.y; r.z += x.z; r.w += x.w;
    }
    ((float4*)out)[i] = r;
}

// ============================================================
// split-K reduce + RMSNorm + RoPE (tables) + k,v scatter.
// ============================================================
__global__ void norm_rope_scatter(const float* __restrict__ q_norm_w,
                                  const float* __restrict__ k_norm_w,
                                  const int* __restrict__ out_cache_loc,
                                  float* __restrict__ k_buf,
                                  float* __restrict__ v_buf) {
    const int head = blockIdx.x;
    const int b = blockIdx.y;
    const int tid = threadIdx.x;
    const int off = b * QKVN + head * D_ + tid;

    float x = 0.f;
    #pragma unroll
    for (int s = 0; s < SPLITK; s++) x += g_part[(size_t)s * (B_ * QKVN) + off];

    if (head >= NH_ + NKV_) {
        int h = head - (NH_ + NKV_);
        int loc = out_cache_loc[b];
        v_buf[(((size_t)b * KV_ + loc) * NKV_ + h) * D_ + tid] = x;
        return;
    }

    __shared__ float sred[4];
    float ss = x * x;
    #pragma unroll
    for (int o = 16; o; o >>= 1) ss += __shfl_xor_sync(0xffffffffu, ss, o);
    if ((tid & 31) == 0) sred[tid >> 5] = ss;
    __syncthreads();
    float total = sred[0] + sred[1] + sred[2] + sred[3];
    float rms = rsqrtf(total * (1.0f / D_) + 1e-6f);
    const float* wn = (head < NH_) ? q_norm_w : k_norm_w;
    float y = x * rms * wn[tid];

    __shared__ float ys[128];
    ys[tid] = y;
    __syncthreads();
    int i = tid & 63;
    float c = g_cosb[b][i], s = g_sinb[b][i];
    float outv = (tid < 64) ? (ys[tid] * c - ys[tid + 64] * s)
                            : (ys[tid] * c + ys[tid - 64] * s);

    if (head < NH_) {
        g_qkv[off] = outv;
    } else {
        int h = head - NH_;
        int loc = out_cache_loc[b];
        k_buf[(((size_t)b * KV_ + loc) * NKV_ + h) * D_ + tid] = outv;
    }
}

// ============================================================
// Fused flash-decode chunk (best-measured form — unchanged).
// ============================================================
__global__ __launch_bounds__(256) void attn_chunk_kernel(
        const float* __restrict__ k_buf, const float* __restrict__ v_buf) {
    const int chunk = blockIdx.x, h = blockIdx.y, b = blockIdx.z;
    const int tid = threadIdx.x;
    const int warp = tid >> 5, lane = tid & 31;

    __shared__ float sbuf[4 * G_ * 64 * 2];
    float (*sc)[CS] = (float(*)[CS])sbuf;
    __shared__ float wred[G_][8];
    __shared__ float gm[G_], gs[G_];

    float4 q4[G_];
    #pragma unroll
    for (int g = 0; g < G_; g++)
        q4[g] = *(const float4*)&g_qkv[b * QKVN + (h * G_ + g) * D_ + lane * 4];

    const int s0 = chunk * CS;
    #pragma unroll 4
    for (int i = warp; i < CS; i += 8) {
        float4 kv = *(const float4*)&k_buf[(((size_t)b * KV_ + s0 + i) * NKV_ + h) * D_ + lane * 4];
        float p[G_];
        #pragma unroll
        for (int g = 0; g < G_; g++)
            p[g] = q4[g].x * kv.x + q4[g].y * kv.y + q4[g].z * kv.z + q4[g].w * kv.w;
        #pragma unroll
        for (int g = 0; g < G_; g++)
            #pragma unroll
            for (int o = 16; o; o >>= 1) p[g] += __shfl_xor_sync(0xffffffffu, p[g], o);
        if (lane == 0) {
            #pragma unroll
            for (int g = 0; g < G_; g++) sc[g][i] = p[g] * SCALE_;
        }
    }
    __syncthreads();

    {
        const int g = tid >> 6;
        const int j = tid & 63;
        float m = -1e30f;
        #pragma unroll
        for (int e = 0; e < CS / 64; e++) m = fmaxf(m, sc[g][j + e * 64]);
        #pragma unroll
        for (int o = 16; o; o >>= 1) m = fmaxf(m, __shfl_xor_sync(0xffffffffu, m, o));
        if (lane == 0) wred[g][warp & 1] = m;
        __syncthreads();
        m = fmaxf(wred[g][0], wred[g][1]);

        float sum = 0.f;
        #pragma unroll
        for (int e = 0; e < CS / 64; e++) {
            float ex = __expf(sc[g][j + e * 64] - m);
            sc[g][j + e * 64] = ex;
            sum += ex;
        }
        #pragma unroll
        for (int o = 16; o; o >>= 1) sum += __shfl_xor_sync(0xffffffffu, sum, o);
        if (lane == 0) wred[g][2 + (warp & 1)] = sum;
        __syncthreads();
        if (j == 0) { gm[g] = m; gs[g] = wred[g][2] + wred[g][3]; }
    }
    __syncthreads();

    const int d2 = tid & 63;
    const int q = tid >> 6;
    float2 acc[G_];
    #pragma unroll
    for (int g = 0; g < G_; g++) acc[g] = make_float2(0.f, 0.f);

    const float* vp = &v_buf[(((size_t)b * KV_ + s0 + q * 64) * NKV_ + h) * D_ + d2 * 2];
    #pragma unroll 8
    for (int sl = 0; sl < 64; sl++) {
        float2 v = *(const float2*)(vp + (size_t)sl * (NKV_ * D_));
        #pragma unroll
        for (int g = 0; g < G_; g++) {
            float p = sc[g][q * 64 + sl];
            acc[g].x += p * v.x;
            acc[g].y += p * v.y;
        }
    }
    __syncthreads();

    float2 (*psh)[G_][64] = (float2(*)[G_][64])sbuf;
    #pragma unroll
    for (int g = 0; g < G_; g++) psh[q][g][d2] = acc[g];
    __syncthreads();

    if (q == 0) {
        const size_t obase = ((((size_t)chunk * B_ + b) * NKV_ + h) * G_) * D_;
        #pragma unroll
        for (int g = 0; g < G_; g++) {
            float2 r0 = psh[0][g][d2], r1 = psh[1][g][d2];
            float2 r2 = psh[2][g][d2], r3 = psh[3][g][d2];
            float2 r = make_float2(r0.x + r1.x + r2.x + r3.x,
                                   r0.y + r1.y + r2.y + r3.y);
            *(float2*)&g_opart[obase + g * D_ + d2 * 2] = r;
        }
        if (d2 < G_) {
            size_t msb = ((((size_t)chunk * B_ + b) * NKV_ + h) * G_ + d2) * 2;
            g_ms[msb] = gm[d2];
            g_ms[msb + 1] = gs[d2];
        }
    }
}

// ============================================================
// Combine chunk partials: grid (NH=32, b=32), 128 threads.
// ============================================================
__global__ void attn_combine_kernel() {
    const int head = blockIdx.x;
    const int b = blockIdx.y;
    const int h = head >> 2, g = head & 3;
    const int d = threadIdx.x;

    float M = -1e30f;
    float mloc[NCHUNK];
    #pragma unroll
    for (int c = 0; c < NCHUNK; c++) {
        size_t msb = ((((size_t)c * B_ + b) * NKV_ + h) * G_ + g) * 2;
        mloc[c] = g_ms[msb];
        M = fmaxf(M, mloc[c]);
    }
    float S = 0.f, o = 0.f;
    #pragma unroll
    for (int c = 0; c < NCHUNK; c++) {
        size_t msb = ((((size_t)c * B_ + b) * NKV_ + h) * G_ + g) * 2;
        float w = __expf(mloc[c] - M);
        S += g_ms[msb + 1] * w;
        o += g_opart[(((((size_t)c * B_ + b) * NKV_ + h) * G_ + g)) * D_ + d] * w;
    }
    g_o[b * (NH_ * D_) + head * D_ + d] = o / S;
}

// ============================================================
extern "C" void kernel_launch(void* const* d_in, const int* in_sizes, int n_in,
                              void* d_out, int out_size) {
    const int*   position_ids  = (const int*)  d_in[0];
    const float* hidden_states = (const float*)d_in[1];
    float*       k_buffer      = (float*)      d_in[2];
    float*       v_buffer      = (float*)      d_in[3];
    const int*   out_cache_loc = (const int*)  d_in[4];
    const float* wqkv          = (const float*)d_in[5];
    const float* wo            = (const float*)d_in[6];
    const float* q_norm_w      = (const float*)d_in[7];
    const float* k_norm_w      = (const float*)d_in[8];
    float* out = (float*)d_out;

    float* part_ptr; cudaGetSymbolAddress((void**)&part_ptr, g_part);
    float* o_ptr;    cudaGetSymbolAddress((void**)&o_ptr, g_o);

    // 1-3. RoPE tables (tiny; keep QKV GEMM in profiler slot 4)
    rope_invf_kernel<<<1, 64>>>();
    rope_cos_kernel<<<B_, 64>>>(position_ids);
    rope_sin_kernel<<<B_, 64>>>(position_ids);
    // 4. QKV projection (SPLITK=16 -> 768 blocks) — profiled
    gemm_splitk<<<dim3(QKVN / 128, SPLITK), 256>>>(hidden_states, wqkv, part_ptr, QKVN, H_);
    // 5. reduce + RMSNorm + RoPE + k,v scatter
    norm_rope_scatter<<<dim3(NH_ + 2 * NKV_, B_), 128>>>(
        q_norm_w, k_norm_w, out_cache_loc, k_buffer, v_buffer);
    // 6. fused flash-decode (split-KV)
    attn_chunk_kernel<<<dim3(NCHUNK, NKV_, B_), 256>>>(k_buffer, v_buffer);
    // 7. combine partials
    attn_combine_kernel<<<dim3(NH_, B_), 128>>>();
    // 8. O projection (SPLITK=16 -> 512 blocks) + 9. reduce
    gemm_splitk<<<dim3(H_ / 128, SPLITK), 256>>>(o_ptr, wo, part_ptr, H_, H_);
    reduce_out<<<(B_ * H_ / 4 + 255) / 256, 256>>>(out, B_ * H_ / 4);
}

// round 12
// speedup vs baseline: 1.0729x; 1.0729x over previous
#include <cuda_runtime.h>
#include <math.h>

#define B_   32
#define KV_  4096
#define H_   4096
#define NH_  32
#define NKV_ 8
#define D_   128
#define G_   4
#define QKVN ((NH_ + 2*NKV_) * D_)   // 6144
#define SCALE_ 0.08838834764831845f  // 128^-0.5
#define SPLITK 16
#define NCHUNK 16
#define CS     (KV_ / NCHUNK)        // 256 slots per chunk

// ---- scratch (device globals: no allocation) ----
__device__ float  g_qkv[B_ * QKVN];
__device__ float  g_part[SPLITK * B_ * QKVN];
__device__ float  g_opart[NCHUNK * B_ * NKV_ * G_ * D_];
__device__ float  g_ms[NCHUNK * B_ * NKV_ * G_ * 2];
__device__ float  g_o[B_ * NH_ * D_];
__device__ double g_invf[64];
__device__ float  g_cosb[B_][64];
__device__ float  g_sinb[B_][64];

// ---- cp.async helpers ----
__device__ __forceinline__ void cp16(void* dst_smem, const void* src) {
    unsigned d = (unsigned)__cvta_generic_to_shared(dst_smem);
    asm volatile("cp.async.cg.shared.global [%0], [%1], 16;" :: "r"(d), "l"(src));
}
__device__ __forceinline__ void cp_commit() { asm volatile("cp.async.commit_group;"); }
__device__ __forceinline__ void cp_wait0()  { asm volatile("cp.async.wait_group 0;" ::: "memory"); }

// ---- tiny prelaunch kernels (keep gemm in profiler slot 4) ----
__global__ void rope_invf_kernel() {
    int i = threadIdx.x;
    if (i < 64) g_invf[i] = pow(1.0e6, -(double)i / 64.0);
}
__global__ void rope_cos_kernel(const int* __restrict__ position_ids) {
    int b = blockIdx.x, i = threadIdx.x;
    g_cosb[b][i] = (float)cos((double)position_ids[b] * g_invf[i]);
}
__global__ void rope_sin_kernel(const int* __restrict__ position_ids) {
    int b = blockIdx.x, i = threadIdx.x;
    g_sinb[b][i] = (float)sin((double)position_ids[b] * g_invf[i]);
}

// ============================================================
// Split-K GEMM, cp.async double-buffered pipeline.
// P[s][32][N] = A[32,kslice] * W[N,kslice]^T
// tile 32(M) x 128(N), k-chunk 32, 256 threads.
// Thread (tx,ty) owns m = ty*4+i, n = n0 + tx + 32*s.
// One __syncthreads per chunk; W never touches registers.
// ============================================================
__global__ __launch_bounds__(256, 4) void gemm_splitk(
        const float* __restrict__ A, const float* __restrict__ W,
        float* __restrict__ P, int N, int K) {
    __shared__ float As[2][32][36];    // [buf][k][m] (transposed at store)
    __shared__ float Ws[2][128][36];   // [buf][n][k] (cp.async, natural layout)
    const int tid = threadIdx.x;
    const int tx = tid & 31, ty = tid >> 5;
    const int n0 = blockIdx.x * 128;
    const int kslice = K / SPLITK;
    const int kbase = blockIdx.y * kslice;
    const int nchunks = kslice / 32;

    // A: 1 float4 per thread, transposed store
    const int m_a = tid >> 3, c_a = (tid & 7) * 4;
    const float* Aptr = &A[m_a * K + kbase + c_a];

    // W: 4 x 16B cp.async per thread per chunk
    const float* Wsrc[4];
    int n_w[4], c_w[4];
    #pragma unroll
    for (int j = 0; j < 4; j++) {
        int f = tid + j * 256;          // 1024 segs = 128 rows x 8 segs
        n_w[j] = f >> 3; c_w[j] = (f & 7) * 4;
        Wsrc[j] = &W[(size_t)(n0 + n_w[j]) * K + kbase + c_w[j]];
    }

    float acc[4][4];                    // [m i][n s]
    #pragma unroll
    for (int i = 0; i < 4; i++)
        #pragma unroll
        for (int s = 0; s < 4; s++) acc[i][s] = 0.f;

    // ---- prologue: chunk 0 in flight ----
    float4 a_reg = *(const float4*)Aptr;
    #pragma unroll
    for (int j = 0; j < 4; j++) cp16(&Ws[0][n_w[j]][c_w[j]], Wsrc[j]);
    cp_commit();
    As[0][c_a + 0][m_a] = a_reg.x; As[0][c_a + 1][m_a] = a_reg.y;
    As[0][c_a + 2][m_a] = a_reg.z; As[0][c_a + 3][m_a] = a_reg.w;

    for (int ck = 0; ck < nchunks; ck++) {
        const int cur = ck & 1, nxt = cur ^ 1;
        cp_wait0();
        __syncthreads();   // Ws[cur]/As[cur] ready; everyone done with [nxt]

        if (ck + 1 < nchunks) {
            #pragma unroll
            for (int j = 0; j < 4; j++)
                cp16(&Ws[nxt][n_w[j]][c_w[j]], Wsrc[j] + (ck + 1) * 32);
            cp_commit();
            a_reg = *(const float4*)(Aptr + (ck + 1) * 32);
        }

        #pragma unroll
        for (int c = 0; c < 8; c++) {
            float4 wv[4];
            #pragma unroll
            for (int s = 0; s < 4; s++)
                wv[s] = *(const float4*)&Ws[cur][tx + 32 * s][c * 4];
            #pragma unroll
            for (int kk = 0; kk < 4; kk++) {
                float4 av = *(const float4*)&As[cur][c * 4 + kk][ty * 4]; // broadcast
                float am[4] = {av.x, av.y, av.z, av.w};
                float wk[4] = {kk == 0 ? wv[0].x : kk == 1 ? wv[0].y : kk == 2 ? wv[0].z : wv[0].w,
                               kk == 0 ? wv[1].x : kk == 1 ? wv[1].y : kk == 2 ? wv[1].z : wv[1].w,
                               kk == 0 ? wv[2].x : kk == 1 ? wv[2].y : kk == 2 ? wv[2].z : wv[2].w,
                               kk == 0 ? wv[3].x : kk == 1 ? wv[3].y : kk == 2 ? wv[3].z : wv[3].w};
                #pragma unroll
                for (int i = 0; i < 4; i++)
                    #pragma unroll
                    for (int s = 0; s < 4; s++) acc[i][s] += am[i] * wk[s];
            }
        }

        if (ck + 1 < nchunks) {
            As[nxt][c_a + 0][m_a] = a_reg.x; As[nxt][c_a + 1][m_a] = a_reg.y;
            As[nxt][c_a + 2][m_a] = a_reg.z; As[nxt][c_a + 3][m_a] = a_reg.w;
        }
    }

    float* p = P + (size_t)blockIdx.y * 32 * N;
    #pragma unroll
    for (int i = 0; i < 4; i++)
        #pragma unroll
        for (int s = 0; s < 4; s++)
            p[(ty * 4 + i) * N + n0 + tx + 32 * s] = acc[i][s];
}

// reduce split-K partials for the O projection into d_out
__global__ void reduce_out(float* __restrict__ out, int total4) {
    int i = blockIdx.x * blockDim.x + threadIdx.x;
    if (i >= total4) return;
    float4 r = make_float4(0.f, 0.f, 0.f, 0.f);
    #pragma unroll
    for (int s = 0; s < SPLITK; s++) {
        float4 x = *(const float4*)&g_part[(size_t)s * (B_ * H_) + i * 4];
        r.x += x.x; r.y += x.y; r.z += x.z; r.w += x.w;
    }
    ((float4*)out)[i] = r;
}

// ============================================================
// split-K reduce + RMSNorm + RoPE (tables) + k,v scatter.
// ============================================================
__global__ void norm_rope_scatter(const float* __restrict__ q_norm_w,
                                  const float* __restrict__ k_norm_w,
                                  const int* __restrict__ out_cache_loc,
                                  float* __restrict__ k_buf,
                                  float* __restrict__ v_buf) {
    const int head = blockIdx.x;
    const int b = blockIdx.y;
    const int tid = threadIdx.x;
    const int off = b * QKVN + head * D_ + tid;

    float x = 0.f;
    #pragma unroll
    for (int s = 0; s < SPLITK; s++) x += g_part[(size_t)s * (B_ * QKVN) + off];

    if (head >= NH_ + NKV_) {
        int h = head - (NH_ + NKV_);
        int loc = out_cache_loc[b];
        v_buf[(((size_t)b * KV_ + loc) * NKV_ + h) * D_ + tid] = x;
        return;
    }

    __shared__ float sred[4];
    float ss = x * x;
    #pragma unroll
    for (int o = 16; o; o >>= 1) ss += __shfl_xor_sync(0xffffffffu, ss, o);
    if ((tid & 31) == 0) sred[tid >> 5] = ss;
    __syncthreads();
    float total = sred[0] + sred[1] + sred[2] + sred[3];
    float rms = rsqrtf(total * (1.0f / D_) + 1e-6f);
    const float* wn = (head < NH_) ? q_norm_w : k_norm_w;
    float y = x * rms * wn[tid];

    __shared__ float ys[128];
    ys[tid] = y;
    __syncthreads();
    int i = tid & 63;
    float c = g_cosb[b][i], s = g_sinb[b][i];
    float outv = (tid < 64) ? (ys[tid] * c - ys[tid + 64] * s)
                            : (ys[tid] * c + ys[tid - 64] * s);

    if (head < NH_) {
        g_qkv[off] = outv;
    } else {
        int h = head - NH_;
        int loc = out_cache_loc[b];
        k_buf[(((size_t)b * KV_ + loc) * NKV_ + h) * D_ + tid] = outv;
    }
}

// ============================================================
// Fused flash-decode chunk (best-measured form — unchanged).
// ============================================================
__global__ __launch_bounds__(256) void attn_chunk_kernel(
        const float* __restrict__ k_buf, const float* __restrict__ v_buf) {
    const int chunk = blockIdx.x, h = blockIdx.y, b = blockIdx.z;
    const int tid = threadIdx.x;
    const int warp = tid >> 5, lane = tid & 31;

    __shared__ float sbuf[4 * G_ * 64 * 2];
    float (*sc)[CS] = (float(*)[CS])sbuf;
    __shared__ float wred[G_][8];
    __shared__ float gm[G_], gs[G_];

    float4 q4[G_];
    #pragma unroll
    for (int g = 0; g < G_; g++)
        q4[g] = *(const float4*)&g_qkv[b * QKVN + (h * G_ + g) * D_ + lane * 4];

    const int s0 = chunk * CS;
    #pragma unroll 4
    for (int i = warp; i < CS; i += 8) {
        float4 kv = *(const float4*)&k_buf[(((size_t)b * KV_ + s0 + i) * NKV_ + h) * D_ + lane * 4];
        float p[G_];
        #pragma unroll
        for (int g = 0; g < G_; g++)
            p[g] = q4[g].x * kv.x + q4[g].y * kv.y + q4[g].z * kv.z + q4[g].w * kv.w;
        #pragma unroll
        for (int g = 0; g < G_; g++)
            #pragma unroll
            for (int o = 16; o; o >>= 1) p[g] += __shfl_xor_sync(0xffffffffu, p[g], o);
        if (lane == 0) {
            #pragma unroll
            for (int g = 0; g < G_; g++) sc[g][i] = p[g] * SCALE_;
        }
    }
    __syncthreads();

    {
        const int g = tid >> 6;
        const int j = tid & 63;
        float m = -1e30f;
        #pragma unroll
        for (int e = 0; e < CS / 64; e++) m = fmaxf(m, sc[g][j + e * 64]);
        #pragma unroll
        for (int o = 16; o; o >>= 1) m = fmaxf(m, __shfl_xor_sync(0xffffffffu, m, o));
        if (lane == 0) wred[g][warp & 1] = m;
        __syncthreads();
        m = fmaxf(wred[g][0], wred[g][1]);

        float sum = 0.f;
        #pragma unroll
        for (int e = 0; e < CS / 64; e++) {
            float ex = __expf(sc[g][j + e * 64] - m);
            sc[g][j + e * 64] = ex;
            sum += ex;
        }
        #pragma unroll
        for (int o = 16; o; o >>= 1) sum += __shfl_xor_sync(0xffffffffu, sum, o);
        if (lane == 0) wred[g][2 + (warp & 1)] = sum;
        __syncthreads();
        if (j == 0) { gm[g] = m; gs[g] = wred[g][2] + wred[g][3]; }
    }
    __syncthreads();

    const int d2 = tid & 63;
    const int q = tid >> 6;
    float2 acc[G_];
    #pragma unroll
    for (int g = 0; g < G_; g++) acc[g] = make_float2(0.f, 0.f);

    const float* vp = &v_buf[(((size_t)b * KV_ + s0 + q * 64) * NKV_ + h) * D_ + d2 * 2];
    #pragma unroll 8
    for (int sl = 0; sl < 64; sl++) {
        float2 v = *(const float2*)(vp + (size_t)sl * (NKV_ * D_));
        #pragma unroll
        for (int g = 0; g < G_; g++) {
            float p = sc[g][q * 64 + sl];
            acc[g].x += p * v.x;
            acc[g].y += p * v.y;
        }
    }
    __syncthreads();

    float2 (*psh)[G_][64] = (float2(*)[G_][64])sbuf;
    #pragma unroll
    for (int g = 0; g < G_; g++) psh[q][g][d2] = acc[g];
    __syncthreads();

    if (q == 0) {
        const size_t obase = ((((size_t)chunk * B_ + b) * NKV_ + h) * G_) * D_;
        #pragma unroll
        for (int g = 0; g < G_; g++) {
            float2 r0 = psh[0][g][d2], r1 = psh[1][g][d2];
            float2 r2 = psh[2][g][d2], r3 = psh[3][g][d2];
            float2 r = make_float2(r0.x + r1.x + r2.x + r3.x,
                                   r0.y + r1.y + r2.y + r3.y);
            *(float2*)&g_opart[obase + g * D_ + d2 * 2] = r;
        }
        if (d2 < G_) {
            size_t msb = ((((size_t)chunk * B_ + b) * NKV_ + h) * G_ + d2) * 2;
            g_ms[msb] = gm[d2];
            g_ms[msb + 1] = gs[d2];
        }
    }
}

// ============================================================
// Combine chunk partials: grid (NH=32, b=32), 128 threads.
// ============================================================
__global__ void attn_combine_kernel() {
    const int head = blockIdx.x;
    const int b = blockIdx.y;
    const int h = head >> 2, g = head & 3;
    const int d = threadIdx.x;

    float M = -1e30f;
    float mloc[NCHUNK];
    #pragma unroll
    for (int c = 0; c < NCHUNK; c++) {
        size_t msb = ((((size_t)c * B_ + b) * NKV_ + h) * G_ + g) * 2;
        mloc[c] = g_ms[msb];
        M = fmaxf(M, mloc[c]);
    }
    float S = 0.f, o = 0.f;
    #pragma unroll
    for (int c = 0; c < NCHUNK; c++) {
        size_t msb = ((((size_t)c * B_ + b) * NKV_ + h) * G_ + g) * 2;
        float w = __expf(mloc[c] - M);
        S += g_ms[msb + 1] * w;
        o += g_opart[(((((size_t)c * B_ + b) * NKV_ + h) * G_ + g)) * D_ + d] * w;
    }
    g_o[b * (NH_ * D_) + head * D_ + d] = o / S;
}

// ============================================================
extern "C" void kernel_launch(void* const* d_in, const int* in_sizes, int n_in,
                              void* d_out, int out_size) {
    const int*   position_ids  = (const int*)  d_in[0];
    const float* hidden_states = (const float*)d_in[1];
    float*       k_buffer      = (float*)      d_in[2];
    float*       v_buffer      = (float*)      d_in[3];
    const int*   out_cache_loc = (const int*)  d_in[4];
    const float* wqkv          = (const float*)d_in[5];
    const float* wo            = (const float*)d_in[6];
    const float* q_norm_w      = (const float*)d_in[7];
    const float* k_norm_w      = (const float*)d_in[8];
    float* out = (float*)d_out;

    float* part_ptr; cudaGetSymbolAddress((void**)&part_ptr, g_part);
    float* o_ptr;    cudaGetSymbolAddress((void**)&o_ptr, g_o);

    // 1-3. RoPE tables (tiny; keep QKV GEMM in profiler slot 4)
    rope_invf_kernel<<<1, 64>>>();
    rope_cos_kernel<<<B_, 64>>>(position_ids);
    rope_sin_kernel<<<B_, 64>>>(position_ids);
    // 4. QKV projection (cp.async pipeline) — profiled
    gemm_splitk<<<dim3(QKVN / 128, SPLITK), 256>>>(hidden_states, wqkv, part_ptr, QKVN, H_);
    // 5. reduce + RMSNorm + RoPE + k,v scatter
    norm_rope_scatter<<<dim3(NH_ + 2 * NKV_, B_), 128>>>(
        q_norm_w, k_norm_w, out_cache_loc, k_buffer, v_buffer);
    // 6. fused flash-decode (split-KV)
    attn_chunk_kernel<<<dim3(NCHUNK, NKV_, B_), 256>>>(k_buffer, v_buffer);
    // 7. combine partials
    attn_combine_kernel<<<dim3(NH_, B_), 128>>>();
    // 8. O projection + 9. reduce
    gemm_splitk<<<dim3(H_ / 128, SPLITK), 256>>>(o_ptr, wo, part_ptr, H_, H_);
    reduce_out<<<(B_ * H_ / 4 + 255) / 256, 256>>>(out, B_ * H_ / 4);
}

// round 13
// speedup vs baseline: 1.2175x; 1.1348x over previous
#include <cuda_runtime.h>
#include <math.h>

#define B_   32
#define KV_  4096
#define H_   4096
#define NH_  32
#define NKV_ 8
#define D_   128
#define G_   4
#define QKVN ((NH_ + 2*NKV_) * D_)   // 6144
#define SCALE_ 0.08838834764831845f  // 128^-0.5
#define SPLITK 16
#define NCHUNK 16
#define CS     (KV_ / NCHUNK)        // 256 slots per chunk

// ---- scratch (device globals: no allocation) ----
__device__ float  g_qkv[B_ * QKVN];
__device__ float  g_part[SPLITK * B_ * QKVN];
__device__ float  g_opart[NCHUNK * B_ * NKV_ * G_ * D_];
__device__ float  g_ms[NCHUNK * B_ * NKV_ * G_ * 2];
__device__ float  g_o[B_ * NH_ * D_];
__device__ double g_invf[64];
__device__ float  g_cosb[B_][64];
__device__ float  g_sinb[B_][64];

// ---- helpers ----
__device__ __forceinline__ void cp16(void* dst_smem, const void* src) {
    unsigned d = (unsigned)__cvta_generic_to_shared(dst_smem);
    asm volatile("cp.async.cg.shared.global [%0], [%1], 16;" :: "r"(d), "l"(src));
}
__device__ __forceinline__ void cp_commit() { asm volatile("cp.async.commit_group;"); }
__device__ __forceinline__ void cp_wait0()  { asm volatile("cp.async.wait_group 0;" ::: "memory"); }
__device__ __forceinline__ unsigned f2tf32(float x) {
    unsigned u;
    asm("cvt.rna.tf32.f32 %0, %1;" : "=r"(u) : "f"(x));
    return u;
}

// ---- tiny prelaunch kernels (keep gemm in profiler slot 4) ----
__global__ void rope_invf_kernel() {
    int i = threadIdx.x;
    if (i < 64) g_invf[i] = pow(1.0e6, -(double)i / 64.0);
}
__global__ void rope_cos_kernel(const int* __restrict__ position_ids) {
    int b = blockIdx.x, i = threadIdx.x;
    g_cosb[b][i] = (float)cos((double)position_ids[b] * g_invf[i]);
}
__global__ void rope_sin_kernel(const int* __restrict__ position_ids) {
    int b = blockIdx.x, i = threadIdx.x;
    g_sinb[b][i] = (float)sin((double)position_ids[b] * g_invf[i]);
}

// ============================================================
// Split-K TF32-MMA GEMM with cp.async double buffering.
// P[s][32][N] = A[32,kslice] * W[N,kslice]^T
// tile 32(M) x 128(N), k-chunk 32, 256 threads (8 warps).
// warp: mt=warp&1 (16 rows), nq=warp>>1 (32 cols = 4 n8-subtiles).
// W: cp.async -> Ws[n][k]; rna-convert in regs; mma.m16n8k8.tf32.
// ============================================================
__global__ __launch_bounds__(256, 4) void gemm_splitk(
        const float* __restrict__ A, const float* __restrict__ W,
        float* __restrict__ P, int N, int K) {
    __shared__ float As[2][32][40];    // [buf][k][m] transposed at store
    __shared__ float Ws[2][128][36];   // [buf][n][k] natural (cp.async)
    const int tid = threadIdx.x;
    const int warp = tid >> 5, lane = tid & 31;
    const int mt = warp & 1;           // m half
    const int nq = warp >> 1;          // n quarter (32 cols)
    const int gi = lane >> 2, ti = lane & 3;
    const int r0 = mt * 16 + gi;
    const int n0 = blockIdx.x * 128;
    const int kslice = K / SPLITK;
    const int kbase = blockIdx.y * kslice;
    const int nchunks = kslice / 32;

    // A: 1 float4 per thread per chunk, transposed store
    const int m_a = tid >> 3, c_a = (tid & 7) * 4;
    const float* Aptr = &A[m_a * K + kbase + c_a];

    // W: 4 x 16B cp.async per thread per chunk
    const float* Wsrc[4];
    int n_w[4], c_w[4];
    #pragma unroll
    for (int j = 0; j < 4; j++) {
        int f = tid + j * 256;
        n_w[j] = f >> 3; c_w[j] = (f & 7) * 4;
        Wsrc[j] = &W[(size_t)(n0 + n_w[j]) * K + kbase + c_w[j]];
    }

    float d[4][4];                      // [n subtile s][reg]
    #pragma unroll
    for (int s = 0; s < 4; s++)
        #pragma unroll
        for (int i = 0; i < 4; i++) d[s][i] = 0.f;

    // ---- prologue ----
    float4 a_reg = *(const float4*)Aptr;
    #pragma unroll
    for (int j = 0; j < 4; j++) cp16(&Ws[0][n_w[j]][c_w[j]], Wsrc[j]);
    cp_commit();
    As[0][c_a + 0][m_a] = a_reg.x; As[0][c_a + 1][m_a] = a_reg.y;
    As[0][c_a + 2][m_a] = a_reg.z; As[0][c_a + 3][m_a] = a_reg.w;

    for (int ck = 0; ck < nchunks; ck++) {
        const int cur = ck & 1, nxt = cur ^ 1;
        cp_wait0();
        __syncthreads();

        if (ck + 1 < nchunks) {
            #pragma unroll
            for (int j = 0; j < 4; j++)
                cp16(&Ws[nxt][n_w[j]][c_w[j]], Wsrc[j] + (ck + 1) * 32);
            cp_commit();
            a_reg = *(const float4*)(Aptr + (ck + 1) * 32);
        }

        #pragma unroll
        for (int c = 0; c < 4; c++) {       // 4 ksteps of 8
            const int k0 = c * 8;
            unsigned a0 = f2tf32(As[cur][k0 + ti][r0]);
            unsigned a1 = f2tf32(As[cur][k0 + ti][r0 + 8]);
            unsigned a2 = f2tf32(As[cur][k0 + ti + 4][r0]);
            unsigned a3 = f2tf32(As[cur][k0 + ti + 4][r0 + 8]);
            #pragma unroll
            for (int s = 0; s < 4; s++) {
                const int nb = nq * 32 + s * 8;
                unsigned b0 = f2tf32(Ws[cur][nb + gi][k0 + ti]);
                unsigned b1 = f2tf32(Ws[cur][nb + gi][k0 + ti + 4]);
                asm volatile(
                    "mma.sync.aligned.m16n8k8.row.col.f32.tf32.tf32.f32 "
                    "{%0,%1,%2,%3}, {%4,%5,%6,%7}, {%8,%9}, {%0,%1,%2,%3};\n"
                    : "+f"(d[s][0]), "+f"(d[s][1]), "+f"(d[s][2]), "+f"(d[s][3])
                    : "r"(a0), "r"(a1), "r"(a2), "r"(a3), "r"(b0), "r"(b1));
            }
        }

        if (ck + 1 < nchunks) {
            As[nxt][c_a + 0][m_a] = a_reg.x; As[nxt][c_a + 1][m_a] = a_reg.y;
            As[nxt][c_a + 2][m_a] = a_reg.z; As[nxt][c_a + 3][m_a] = a_reg.w;
        }
    }

    // write-out: d0/d1 -> (r0, 2ti..), d2/d3 -> (r0+8, ...)
    float* p = P + (size_t)blockIdx.y * 32 * N;
    #pragma unroll
    for (int s = 0; s < 4; s++) {
        const int col = n0 + nq * 32 + s * 8 + ti * 2;
        *(float2*)&p[r0 * N + col] = make_float2(d[s][0], d[s][1]);
        *(float2*)&p[(r0 + 8) * N + col] = make_float2(d[s][2], d[s][3]);
    }
}

// reduce split-K partials for the O projection into d_out
__global__ void reduce_out(float* __restrict__ out, int total4) {
    int i = blockIdx.x * blockDim.x + threadIdx.x;
    if (i >= total4) return;
    float4 r = make_float4(0.f, 0.f, 0.f, 0.f);
    #pragma unroll
    for (int s = 0; s < SPLITK; s++) {
        float4 x = *(const float4*)&g_part[(size_t)s * (B_ * H_) + i * 4];
        r.x += x.x; r.y += x.y; r.z += x.z; r.w += x.w;
    }
    ((float4*)out)[i] = r;
}

// ============================================================
// split-K reduce + RMSNorm + RoPE (tables) + k,v scatter.
// ============================================================
__global__ void norm_rope_scatter(const float* __restrict__ q_norm_w,
                                  const float* __restrict__ k_norm_w,
                                  const int* __restrict__ out_cache_loc,
                                  float* __restrict__ k_buf,
                                  float* __restrict__ v_buf) {
    const int head = blockIdx.x;
    const int b = blockIdx.y;
    const int tid = threadIdx.x;
    const int off = b * QKVN + head * D_ + tid;

    float x = 0.f;
    #pragma unroll
    for (int s = 0; s < SPLITK; s++) x += g_part[(size_t)s * (B_ * QKVN) + off];

    if (head >= NH_ + NKV_) {
        int h = head - (NH_ + NKV_);
        int loc = out_cache_loc[b];
        v_buf[(((size_t)b * KV_ + loc) * NKV_ + h) * D_ + tid] = x;
        return;
    }

    __shared__ float sred[4];
    float ss = x * x;
    #pragma unroll
    for (int o = 16; o; o >>= 1) ss += __shfl_xor_sync(0xffffffffu, ss, o);
    if ((tid & 31) == 0) sred[tid >> 5] = ss;
    __syncthreads();
    float total = sred[0] + sred[1] + sred[2] + sred[3];
    float rms = rsqrtf(total * (1.0f / D_) + 1e-6f);
    const float* wn = (head < NH_) ? q_norm_w : k_norm_w;
    float y = x * rms * wn[tid];

    __shared__ float ys[128];
    ys[tid] = y;
    __syncthreads();
    int i = tid & 63;
    float c = g_cosb[b][i], s = g_sinb[b][i];
    float outv = (tid < 64) ? (ys[tid] * c - ys[tid + 64] * s)
                            : (ys[tid] * c + ys[tid - 64] * s);

    if (head < NH_) {
        g_qkv[off] = outv;
    } else {
        int h = head - NH_;
        int loc = out_cache_loc[b];
        k_buf[(((size_t)b * KV_ + loc) * NKV_ + h) * D_ + tid] = outv;
    }
}

// ============================================================
// Fused flash-decode chunk (best-measured form — unchanged).
// ============================================================
__global__ __launch_bounds__(256) void attn_chunk_kernel(
        const float* __restrict__ k_buf, const float* __restrict__ v_buf) {
    const int chunk = blockIdx.x, h = blockIdx.y, b = blockIdx.z;
    const int tid = threadIdx.x;
    const int warp = tid >> 5, lane = tid & 31;

    __shared__ float sbuf[4 * G_ * 64 * 2];
    float (*sc)[CS] = (float(*)[CS])sbuf;
    __shared__ float wred[G_][8];
    __shared__ float gm[G_], gs[G_];

    float4 q4[G_];
    #pragma unroll
    for (int g = 0; g < G_; g++)
        q4[g] = *(const float4*)&g_qkv[b * QKVN + (h * G_ + g) * D_ + lane * 4];

    const int s0 = chunk * CS;
    #pragma unroll 4
    for (int i = warp; i < CS; i += 8) {
        float4 kv = *(const float4*)&k_buf[(((size_t)b * KV_ + s0 + i) * NKV_ + h) * D_ + lane * 4];
        float p[G_];
        #pragma unroll
        for (int g = 0; g < G_; g++)
            p[g] = q4[g].x * kv.x + q4[g].y * kv.y + q4[g].z * kv.z + q4[g].w * kv.w;
        #pragma unroll
        for (int g = 0; g < G_; g++)
            #pragma unroll
            for (int o = 16; o; o >>= 1) p[g] += __shfl_xor_sync(0xffffffffu, p[g], o);
        if (lane == 0) {
            #pragma unroll
            for (int g = 0; g < G_; g++) sc[g][i] = p[g] * SCALE_;
        }
    }
    __syncthreads();

    {
        const int g = tid >> 6;
        const int j = tid & 63;
        float m = -1e30f;
        #pragma unroll
        for (int e = 0; e < CS / 64; e++) m = fmaxf(m, sc[g][j + e * 64]);
        #pragma unroll
        for (int o = 16; o; o >>= 1) m = fmaxf(m, __shfl_xor_sync(0xffffffffu, m, o));
        if (lane == 0) wred[g][warp & 1] = m;
        __syncthreads();
        m = fmaxf(wred[g][0], wred[g][1]);

        float sum = 0.f;
        #pragma unroll
        for (int e = 0; e < CS / 64; e++) {
            float ex = __expf(sc[g][j + e * 64] - m);
            sc[g][j + e * 64] = ex;
            sum += ex;
        }
        #pragma unroll
        for (int o = 16; o; o >>= 1) sum += __shfl_xor_sync(0xffffffffu, sum, o);
        if (lane == 0) wred[g][2 + (warp & 1)] = sum;
        __syncthreads();
        if (j == 0) { gm[g] = m; gs[g] = wred[g][2] + wred[g][3]; }
    }
    __syncthreads();

    const int d2 = tid & 63;
    const int q = tid >> 6;
    float2 acc[G_];
    #pragma unroll
    for (int g = 0; g < G_; g++) acc[g] = make_float2(0.f, 0.f);

    const float* vp = &v_buf[(((size_t)b * KV_ + s0 + q * 64) * NKV_ + h) * D_ + d2 * 2];
    #pragma unroll 8
    for (int sl = 0; sl < 64; sl++) {
        float2 v = *(const float2*)(vp + (size_t)sl * (NKV_ * D_));
        #pragma unroll
        for (int g = 0; g < G_; g++) {
            float p = sc[g][q * 64 + sl];
            acc[g].x += p * v.x;
            acc[g].y += p * v.y;
        }
    }
    __syncthreads();

    float2 (*psh)[G_][64] = (float2(*)[G_][64])sbuf;
    #pragma unroll
    for (int g = 0; g < G_; g++) psh[q][g][d2] = acc[g];
    __syncthreads();

    if (q == 0) {
        const size_t obase = ((((size_t)chunk * B_ + b) * NKV_ + h) * G_) * D_;
        #pragma unroll
        for (int g = 0; g < G_; g++) {
            float2 r0 = psh[0][g][d2], r1 = psh[1][g][d2];
            float2 r2 = psh[2][g][d2], r3 = psh[3][g][d2];
            float2 r = make_float2(r0.x + r1.x + r2.x + r3.x,
                                   r0.y + r1.y + r2.y + r3.y);
            *(float2*)&g_opart[obase + g * D_ + d2 * 2] = r;
        }
        if (d2 < G_) {
            size_t msb = ((((size_t)chunk * B_ + b) * NKV_ + h) * G_ + d2) * 2;
            g_ms[msb] = gm[d2];
            g_ms[msb + 1] = gs[d2];
        }
    }
}

// ============================================================
// Combine chunk partials: grid (NH=32, b=32), 128 threads.
// ============================================================
__global__ void attn_combine_kernel() {
    const int head = blockIdx.x;
    const int b = blockIdx.y;
    const int h = head >> 2, g = head & 3;
    const int d = threadIdx.x;

    float M = -1e30f;
    float mloc[NCHUNK];
    #pragma unroll
    for (int c = 0; c < NCHUNK; c++) {
        size_t msb = ((((size_t)c * B_ + b) * NKV_ + h) * G_ + g) * 2;
        mloc[c] = g_ms[msb];
        M = fmaxf(M, mloc[c]);
    }
    float S = 0.f, o = 0.f;
    #pragma unroll
    for (int c = 0; c < NCHUNK; c++) {
        size_t msb = ((((size_t)c * B_ + b) * NKV_ + h) * G_ + g) * 2;
        float w = __expf(mloc[c] - M);
        S += g_ms[msb + 1] * w;
        o += g_opart[(((((size_t)c * B_ + b) * NKV_ + h) * G_ + g)) * D_ + d] * w;
    }
    g_o[b * (NH_ * D_) + head * D_ + d] = o / S;
}

// ============================================================
extern "C" void kernel_launch(void* const* d_in, const int* in_sizes, int n_in,
                              void* d_out, int out_size) {
    const int*   position_ids  = (const int*)  d_in[0];
    const float* hidden_states = (const float*)d_in[1];
    float*       k_buffer      = (float*)      d_in[2];
    float*       v_buffer      = (float*)      d_in[3];
    const int*   out_cache_loc = (const int*)  d_in[4];
    const float* wqkv          = (const float*)d_in[5];
    const float* wo            = (const float*)d_in[6];
    const float* q_norm_w      = (const float*)d_in[7];
    const float* k_norm_w      = (const float*)d_in[8];
    float* out = (float*)d_out;

    float* part_ptr; cudaGetSymbolAddress((void**)&part_ptr, g_part);
    float* o_ptr;    cudaGetSymbolAddress((void**)&o_ptr, g_o);

    // 1-3. RoPE tables (tiny; keep QKV GEMM in profiler slot 4)
    rope_invf_kernel<<<1, 64>>>();
    rope_cos_kernel<<<B_, 64>>>(position_ids);
    rope_sin_kernel<<<B_, 64>>>(position_ids);
    // 4. QKV projection (tf32 MMA + cp.async) — profiled
    gemm_splitk<<<dim3(QKVN / 128, SPLITK), 256>>>(hidden_states, wqkv, part_ptr, QKVN, H_);
    // 5. reduce + RMSNorm + RoPE + k,v scatter
    norm_rope_scatter<<<dim3(NH_ + 2 * NKV_, B_), 128>>>(
        q_norm_w, k_norm_w, out_cache_loc, k_buffer, v_buffer);
    // 6. fused flash-decode (split-KV)
    attn_chunk_kernel<<<dim3(NCHUNK, NKV_, B_), 256>>>(k_buffer, v_buffer);
    // 7. combine partials
    attn_combine_kernel<<<dim3(NH_, B_), 128>>>();
    // 8. O projection + 9. reduce
    gemm_splitk<<<dim3(H_ / 128, SPLITK), 256>>>(o_ptr, wo, part_ptr, H_, H_);
    reduce_out<<<(B_ * H_ / 4 + 255) / 256, 256>>>(out, B_ * H_ / 4);
}

// round 14
// speedup vs baseline: 1.2190x; 1.0012x over previous
#include <cuda_runtime.h>
#include <math.h>

#define B_   32
#define KV_  4096
#define H_   4096
#define NH_  32
#define NKV_ 8
#define D_   128
#define G_   4
#define QKVN ((NH_ + 2*NKV_) * D_)   // 6144
#define SCALE_ 0.08838834764831845f  // 128^-0.5
#define SPLITK 16
#define NCHUNK 16
#define CS     (KV_ / NCHUNK)        // 256 slots per chunk

// ---- scratch (device globals: no allocation) ----
__device__ float  g_qkv[B_ * QKVN];
__device__ float  g_part[SPLITK * B_ * QKVN];
__device__ float  g_opart[NCHUNK * B_ * NKV_ * G_ * D_];
__device__ float  g_ms[NCHUNK * B_ * NKV_ * G_ * 2];
__device__ float  g_o[B_ * NH_ * D_];
__device__ float  g_cosb[B_][64];
__device__ float  g_sinb[B_][64];

// ---- helpers ----
__device__ __forceinline__ void cp16(void* dst_smem, const void* src) {
    unsigned d = (unsigned)__cvta_generic_to_shared(dst_smem);
    asm volatile("cp.async.cg.shared.global [%0], [%1], 16;" :: "r"(d), "l"(src));
}
__device__ __forceinline__ void cp_commit() { asm volatile("cp.async.commit_group;"); }
__device__ __forceinline__ void cp_wait0()  { asm volatile("cp.async.wait_group 0;" ::: "memory"); }
__device__ __forceinline__ unsigned f2tf32(float x) {
    unsigned u;
    asm("cvt.rna.tf32.f32 %0, %1;" : "=r"(u) : "f"(x));
    return u;
}

// ---- RoPE tables: one kernel, grid (B_), 64 threads ----
__global__ void rope_tables_kernel(const int* __restrict__ position_ids) {
    int b = blockIdx.x, i = threadIdx.x;
    double invf = pow(1.0e6, -(double)i / 64.0);
    double ang = (double)position_ids[b] * invf;
    g_cosb[b][i] = (float)cos(ang);
    g_sinb[b][i] = (float)sin(ang);
}

// ============================================================
// Split-K TF32-MMA GEMM with cp.async double buffering (R13 form).
// ============================================================
__global__ __launch_bounds__(256, 4) void gemm_splitk(
        const float* __restrict__ A, const float* __restrict__ W,
        float* __restrict__ P, int N, int K) {
    __shared__ float As[2][32][40];
    __shared__ float Ws[2][128][36];
    const int tid = threadIdx.x;
    const int warp = tid >> 5, lane = tid & 31;
    const int mt = warp & 1;
    const int nq = warp >> 1;
    const int gi = lane >> 2, ti = lane & 3;
    const int r0 = mt * 16 + gi;
    const int n0 = blockIdx.x * 128;
    const int kslice = K / SPLITK;
    const int kbase = blockIdx.y * kslice;
    const int nchunks = kslice / 32;

    const int m_a = tid >> 3, c_a = (tid & 7) * 4;
    const float* Aptr = &A[m_a * K + kbase + c_a];

    const float* Wsrc[4];
    int n_w[4], c_w[4];
    #pragma unroll
    for (int j = 0; j < 4; j++) {
        int f = tid + j * 256;
        n_w[j] = f >> 3; c_w[j] = (f & 7) * 4;
        Wsrc[j] = &W[(size_t)(n0 + n_w[j]) * K + kbase + c_w[j]];
    }

    float d[4][4];
    #pragma unroll
    for (int s = 0; s < 4; s++)
        #pragma unroll
        for (int i = 0; i < 4; i++) d[s][i] = 0.f;

    float4 a_reg = *(const float4*)Aptr;
    #pragma unroll
    for (int j = 0; j < 4; j++) cp16(&Ws[0][n_w[j]][c_w[j]], Wsrc[j]);
    cp_commit();
    As[0][c_a + 0][m_a] = a_reg.x; As[0][c_a + 1][m_a] = a_reg.y;
    As[0][c_a + 2][m_a] = a_reg.z; As[0][c_a + 3][m_a] = a_reg.w;

    for (int ck = 0; ck < nchunks; ck++) {
        const int cur = ck & 1, nxt = cur ^ 1;
        cp_wait0();
        __syncthreads();

        if (ck + 1 < nchunks) {
            #pragma unroll
            for (int j = 0; j < 4; j++)
                cp16(&Ws[nxt][n_w[j]][c_w[j]], Wsrc[j] + (ck + 1) * 32);
            cp_commit();
            a_reg = *(const float4*)(Aptr + (ck + 1) * 32);
        }

        #pragma unroll
        for (int c = 0; c < 4; c++) {
            const int k0 = c * 8;
            unsigned a0 = f2tf32(As[cur][k0 + ti][r0]);
            unsigned a1 = f2tf32(As[cur][k0 + ti][r0 + 8]);
            unsigned a2 = f2tf32(As[cur][k0 + ti + 4][r0]);
            unsigned a3 = f2tf32(As[cur][k0 + ti + 4][r0 + 8]);
            #pragma unroll
            for (int s = 0; s < 4; s++) {
                const int nb = nq * 32 + s * 8;
                unsigned b0 = f2tf32(Ws[cur][nb + gi][k0 + ti]);
                unsigned b1 = f2tf32(Ws[cur][nb + gi][k0 + ti + 4]);
                asm volatile(
                    "mma.sync.aligned.m16n8k8.row.col.f32.tf32.tf32.f32 "
                    "{%0,%1,%2,%3}, {%4,%5,%6,%7}, {%8,%9}, {%0,%1,%2,%3};\n"
                    : "+f"(d[s][0]), "+f"(d[s][1]), "+f"(d[s][2]), "+f"(d[s][3])
                    : "r"(a0), "r"(a1), "r"(a2), "r"(a3), "r"(b0), "r"(b1));
            }
        }

        if (ck + 1 < nchunks) {
            As[nxt][c_a + 0][m_a] = a_reg.x; As[nxt][c_a + 1][m_a] = a_reg.y;
            As[nxt][c_a + 2][m_a] = a_reg.z; As[nxt][c_a + 3][m_a] = a_reg.w;
        }
    }

    float* p = P + (size_t)blockIdx.y * 32 * N;
    #pragma unroll
    for (int s = 0; s < 4; s++) {
        const int col = n0 + nq * 32 + s * 8 + ti * 2;
        *(float2*)&p[r0 * N + col] = make_float2(d[s][0], d[s][1]);
        *(float2*)&p[(r0 + 8) * N + col] = make_float2(d[s][2], d[s][3]);
    }
}

// reduce split-K partials for the O projection into d_out
__global__ void reduce_out(float* __restrict__ out, int total4) {
    int i = blockIdx.x * blockDim.x + threadIdx.x;
    if (i >= total4) return;
    float4 r = make_float4(0.f, 0.f, 0.f, 0.f);
    #pragma unroll
    for (int s = 0; s < SPLITK; s++) {
        float4 x = *(const float4*)&g_part[(size_t)s * (B_ * H_) + i * 4];
        r.x += x.x; r.y += x.y; r.z += x.z; r.w += x.w;
    }
    ((float4*)out)[i] = r;
}

// ============================================================
// split-K reduce + RMSNorm + RoPE (tables) + k,v scatter.
// ============================================================
__global__ void norm_rope_scatter(const float* __restrict__ q_norm_w,
                                  const float* __restrict__ k_norm_w,
                                  const int* __restrict__ out_cache_loc,
                                  float* __restrict__ k_buf,
                                  float* __restrict__ v_buf) {
    const int head = blockIdx.x;
    const int b = blockIdx.y;
    const int tid = threadIdx.x;
    const int off = b * QKVN + head * D_ + tid;

    float x = 0.f;
    #pragma unroll
    for (int s = 0; s < SPLITK; s++) x += g_part[(size_t)s * (B_ * QKVN) + off];

    if (head >= NH_ + NKV_) {
        int h = head - (NH_ + NKV_);
        int loc = out_cache_loc[b];
        v_buf[(((size_t)b * KV_ + loc) * NKV_ + h) * D_ + tid] = x;
        return;
    }

    __shared__ float sred[4];
    float ss = x * x;
    #pragma unroll
    for (int o = 16; o; o >>= 1) ss += __shfl_xor_sync(0xffffffffu, ss, o);
    if ((tid & 31) == 0) sred[tid >> 5] = ss;
    __syncthreads();
    float total = sred[0] + sred[1] + sred[2] + sred[3];
    float rms = rsqrtf(total * (1.0f / D_) + 1e-6f);
    const float* wn = (head < NH_) ? q_norm_w : k_norm_w;
    float y = x * rms * wn[tid];

    __shared__ float ys[128];
    ys[tid] = y;
    __syncthreads();
    int i = tid & 63;
    float c = g_cosb[b][i], s = g_sinb[b][i];
    float outv = (tid < 64) ? (ys[tid] * c - ys[tid + 64] * s)
                            : (ys[tid] * c + ys[tid - 64] * s);

    if (head < NH_) {
        g_qkv[off] = outv;
    } else {
        int h = head - NH_;
        int loc = out_cache_loc[b];
        k_buf[(((size_t)b * KV_ + loc) * NKV_ + h) * D_ + tid] = outv;
    }
}

// ============================================================
// Fused flash-decode chunk — forced 6 CTAs/SM for higher MLP.
// grid (chunk=16, h=8, b=32) = 4096 blocks, 256 threads.
// ============================================================
__global__ __launch_bounds__(256, 6) void attn_chunk_kernel(
        const float* __restrict__ k_buf, const float* __restrict__ v_buf) {
    const int chunk = blockIdx.x, h = blockIdx.y, b = blockIdx.z;
    const int tid = threadIdx.x;
    const int warp = tid >> 5, lane = tid & 31;

    __shared__ float sbuf[4 * G_ * 64 * 2];
    float (*sc)[CS] = (float(*)[CS])sbuf;
    __shared__ float wred[G_][8];
    __shared__ float gm[G_], gs[G_];

    float4 q4[G_];
    #pragma unroll
    for (int g = 0; g < G_; g++)
        q4[g] = *(const float4*)&g_qkv[b * QKVN + (h * G_ + g) * D_ + lane * 4];

    const int s0 = chunk * CS;
    #pragma unroll 4
    for (int i = warp; i < CS; i += 8) {
        float4 kv = *(const float4*)&k_buf[(((size_t)b * KV_ + s0 + i) * NKV_ + h) * D_ + lane * 4];
        float p[G_];
        #pragma unroll
        for (int g = 0; g < G_; g++)
            p[g] = q4[g].x * kv.x + q4[g].y * kv.y + q4[g].z * kv.z + q4[g].w * kv.w;
        #pragma unroll
        for (int g = 0; g < G_; g++)
            #pragma unroll
            for (int o = 16; o; o >>= 1) p[g] += __shfl_xor_sync(0xffffffffu, p[g], o);
        if (lane == 0) {
            #pragma unroll
            for (int g = 0; g < G_; g++) sc[g][i] = p[g] * SCALE_;
        }
    }
    __syncthreads();

    {
        const int g = tid >> 6;
        const int j = tid & 63;
        float m = -1e30f;
        #pragma unroll
        for (int e = 0; e < CS / 64; e++) m = fmaxf(m, sc[g][j + e * 64]);
        #pragma unroll
        for (int o = 16; o; o >>= 1) m = fmaxf(m, __shfl_xor_sync(0xffffffffu, m, o));
        if (lane == 0) wred[g][warp & 1] = m;
        __syncthreads();
        m = fmaxf(wred[g][0], wred[g][1]);

        float sum = 0.f;
        #pragma unroll
        for (int e = 0; e < CS / 64; e++) {
            float ex = __expf(sc[g][j + e * 64] - m);
            sc[g][j + e * 64] = ex;
            sum += ex;
        }
        #pragma unroll
        for (int o = 16; o; o >>= 1) sum += __shfl_xor_sync(0xffffffffu, sum, o);
        if (lane == 0) wred[g][2 + (warp & 1)] = sum;
        __syncthreads();
        if (j == 0) { gm[g] = m; gs[g] = wred[g][2] + wred[g][3]; }
    }
    __syncthreads();

    const int d2 = tid & 63;
    const int q = tid >> 6;
    float2 acc[G_];
    #pragma unroll
    for (int g = 0; g < G_; g++) acc[g] = make_float2(0.f, 0.f);

    const float* vp = &v_buf[(((size_t)b * KV_ + s0 + q * 64) * NKV_ + h) * D_ + d2 * 2];
    #pragma unroll 8
    for (int sl = 0; sl < 64; sl++) {
        float2 v = *(const float2*)(vp + (size_t)sl * (NKV_ * D_));
        #pragma unroll
        for (int g = 0; g < G_; g++) {
            float p = sc[g][q * 64 + sl];
            acc[g].x += p * v.x;
            acc[g].y += p * v.y;
        }
    }
    __syncthreads();

    float2 (*psh)[G_][64] = (float2(*)[G_][64])sbuf;
    #pragma unroll
    for (int g = 0; g < G_; g++) psh[q][g][d2] = acc[g];
    __syncthreads();

    if (q == 0) {
        const size_t obase = ((((size_t)chunk * B_ + b) * NKV_ + h) * G_) * D_;
        #pragma unroll
        for (int g = 0; g < G_; g++) {
            float2 r0 = psh[0][g][d2], r1 = psh[1][g][d2];
            float2 r2 = psh[2][g][d2], r3 = psh[3][g][d2];
            float2 r = make_float2(r0.x + r1.x + r2.x + r3.x,
                                   r0.y + r1.y + r2.y + r3.y);
            *(float2*)&g_opart[obase + g * D_ + d2 * 2] = r;
        }
        if (d2 < G_) {
            size_t msb = ((((size_t)chunk * B_ + b) * NKV_ + h) * G_ + d2) * 2;
            g_ms[msb] = gm[d2];
            g_ms[msb + 1] = gs[d2];
        }
    }
}

// ============================================================
// Combine chunk partials: grid (NH=32, b=32), 128 threads.
// ============================================================
__global__ void attn_combine_kernel() {
    const int head = blockIdx.x;
    const int b = blockIdx.y;
    const int h = head >> 2, g = head & 3;
    const int d = threadIdx.x;

    float M = -1e30f;
    float mloc[NCHUNK];
    #pragma unroll
    for (int c = 0; c < NCHUNK; c++) {
        size_t msb = ((((size_t)c * B_ + b) * NKV_ + h) * G_ + g) * 2;
        mloc[c] = g_ms[msb];
        M = fmaxf(M, mloc[c]);
    }
    float S = 0.f, o = 0.f;
    #pragma unroll
    for (int c = 0; c < NCHUNK; c++) {
        size_t msb = ((((size_t)c * B_ + b) * NKV_ + h) * G_ + g) * 2;
        float w = __expf(mloc[c] - M);
        S += g_ms[msb + 1] * w;
        o += g_opart[(((((size_t)c * B_ + b) * NKV_ + h) * G_ + g)) * D_ + d] * w;
    }
    g_o[b * (NH_ * D_) + head * D_ + d] = o / S;
}

// ============================================================
extern "C" void kernel_launch(void* const* d_in, const int* in_sizes, int n_in,
                              void* d_out, int out_size) {
    const int*   position_ids  = (const int*)  d_in[0];
    const float* hidden_states = (const float*)d_in[1];
    float*       k_buffer      = (float*)      d_in[2];
    float*       v_buffer      = (float*)      d_in[3];
    const int*   out_cache_loc = (const int*)  d_in[4];
    const float* wqkv          = (const float*)d_in[5];
    const float* wo            = (const float*)d_in[6];
    const float* q_norm_w      = (const float*)d_in[7];
    const float* k_norm_w      = (const float*)d_in[8];
    float* out = (float*)d_out;

    float* part_ptr; cudaGetSymbolAddress((void**)&part_ptr, g_part);
    float* o_ptr;    cudaGetSymbolAddress((void**)&o_ptr, g_o);

    // 1. RoPE tables (one kernel)
    rope_tables_kernel<<<B_, 64>>>(position_ids);
    // 2. QKV projection (tf32 MMA + cp.async)
    gemm_splitk<<<dim3(QKVN / 128, SPLITK), 256>>>(hidden_states, wqkv, part_ptr, QKVN, H_);
    // 3. reduce + RMSNorm + RoPE + k,v scatter
    norm_rope_scatter<<<dim3(NH_ + 2 * NKV_, B_), 128>>>(
        q_norm_w, k_norm_w, out_cache_loc, k_buffer, v_buffer);
    // 4. fused flash-decode — profiled this round
    attn_chunk_kernel<<<dim3(NCHUNK, NKV_, B_), 256>>>(k_buffer, v_buffer);
    // 5. combine partials
    attn_combine_kernel<<<dim3(NH_, B_), 128>>>();
    // 6. O projection + 7. reduce
    gemm_splitk<<<dim3(H_ / 128, SPLITK), 256>>>(o_ptr, wo, part_ptr, H_, H_);
    reduce_out<<<(B_ * H_ / 4 + 255) / 256, 256>>>(out, B_ * H_ / 4);
}

// round 15
// speedup vs baseline: 1.2480x; 1.0238x over previous
#include <cuda_runtime.h>
#include <math.h>

#define B_   32
#define KV_  4096
#define H_   4096
#define NH_  32
#define NKV_ 8
#define D_   128
#define G_   4
#define QKVN ((NH_ + 2*NKV_) * D_)   // 6144
#define SCALE_ 0.08838834764831845f  // 128^-0.5
#define SPLITK 16
#define NCHUNK 16
#define CS     (KV_ / NCHUNK)        // 256 slots per chunk
#define STAGES 3

// ---- scratch (device globals: no allocation) ----
__device__ float  g_qkv[B_ * QKVN];
__device__ float  g_part[SPLITK * B_ * QKVN];
__device__ float  g_opart[NCHUNK * B_ * NKV_ * G_ * D_];
__device__ float  g_ms[NCHUNK * B_ * NKV_ * G_ * 2];
__device__ float  g_o[B_ * NH_ * D_];
__device__ float  g_cosb[B_][64];
__device__ float  g_sinb[B_][64];

// ---- helpers ----
__device__ __forceinline__ void cp16(void* dst_smem, const void* src) {
    unsigned d = (unsigned)__cvta_generic_to_shared(dst_smem);
    asm volatile("cp.async.cg.shared.global [%0], [%1], 16;" :: "r"(d), "l"(src));
}
__device__ __forceinline__ void cp_commit() { asm volatile("cp.async.commit_group;"); }
__device__ __forceinline__ void cp_wait1()  { asm volatile("cp.async.wait_group 1;" ::: "memory"); }
__device__ __forceinline__ unsigned f2tf32(float x) {
    unsigned u;
    asm("cvt.rna.tf32.f32 %0, %1;" : "=r"(u) : "f"(x));
    return u;
}

// ---- RoPE tables: one kernel, grid (B_), 64 threads ----
__global__ void rope_tables_kernel(const int* __restrict__ position_ids) {
    int b = blockIdx.x, i = threadIdx.x;
    double invf = pow(1.0e6, -(double)i / 64.0);
    double ang = (double)position_ids[b] * invf;
    g_cosb[b][i] = (float)cos(ang);
    g_sinb[b][i] = (float)sin(ang);
}

// ============================================================
// Split-K TF32-MMA GEMM, 3-stage cp.async pipeline (depth-2).
// P[s][32][N] = A[32,kslice] * W[N,kslice]^T
// tile 32(M) x 128(N), k-chunk 32, 256 threads (8 warps).
// Both A and W staged via cp.async in natural [row][k] layout.
// ============================================================
__global__ __launch_bounds__(256, 3) void gemm_splitk(
        const float* __restrict__ A, const float* __restrict__ W,
        float* __restrict__ P, int N, int K) {
    __shared__ float As[STAGES][32][36];    // [st][m][k], natural
    __shared__ float Ws[STAGES][128][36];   // [st][n][k], natural
    const int tid = threadIdx.x;
    const int warp = tid >> 5, lane = tid & 31;
    const int mt = warp & 1;
    const int nq = warp >> 1;
    const int gi = lane >> 2, ti = lane & 3;
    const int r0 = mt * 16 + gi;
    const int n0 = blockIdx.x * 128;
    const int kslice = K / SPLITK;
    const int kbase = blockIdx.y * kslice;
    const int nchunks = kslice / 32;

    // A: 1 x 16B cp.async per thread per chunk (32 rows x 8 segs)
    const int m_a = tid >> 3, c_a = (tid & 7) * 4;
    const float* Asrc = &A[m_a * K + kbase + c_a];

    // W: 4 x 16B cp.async per thread per chunk
    const float* Wsrc[4];
    int n_w[4], c_w[4];
    #pragma unroll
    for (int j = 0; j < 4; j++) {
        int f = tid + j * 256;
        n_w[j] = f >> 3; c_w[j] = (f & 7) * 4;
        Wsrc[j] = &W[(size_t)(n0 + n_w[j]) * K + kbase + c_w[j]];
    }

    float d[4][4];
    #pragma unroll
    for (int s = 0; s < 4; s++)
        #pragma unroll
        for (int i = 0; i < 4; i++) d[s][i] = 0.f;

    // ---- prologue: chunks 0 and 1 in flight (2 groups) ----
    #pragma unroll
    for (int pc = 0; pc < 2; pc++) {
        if (pc < nchunks) {
            cp16(&As[pc][m_a][c_a], Asrc + pc * 32);
            #pragma unroll
            for (int j = 0; j < 4; j++)
                cp16(&Ws[pc][n_w[j]][c_w[j]], Wsrc[j] + pc * 32);
        }
        cp_commit();
    }

    for (int ck = 0; ck < nchunks; ck++) {
        const int cur = ck % STAGES;
        cp_wait1();        // groups 0..ck complete (1 commit per iter below)
        __syncthreads();   // all warps done computing chunk ck-1

        {                  // issue chunk ck+2 into buffer (ck+2)%STAGES
            const int pf = ck + 2;
            if (pf < nchunks) {
                const int st = pf % STAGES;
                cp16(&As[st][m_a][c_a], Asrc + pf * 32);
                #pragma unroll
                for (int j = 0; j < 4; j++)
                    cp16(&Ws[st][n_w[j]][c_w[j]], Wsrc[j] + pf * 32);
            }
            cp_commit();   // unconditional: keeps group numbering aligned
        }

        #pragma unroll
        for (int c = 0; c < 4; c++) {
            const int k0 = c * 8;
            unsigned a0 = f2tf32(As[cur][r0][k0 + ti]);
            unsigned a1 = f2tf32(As[cur][r0 + 8][k0 + ti]);
            unsigned a2 = f2tf32(As[cur][r0][k0 + ti + 4]);
            unsigned a3 = f2tf32(As[cur][r0 + 8][k0 + ti + 4]);
            #pragma unroll
            for (int s = 0; s < 4; s++) {
                const int nb = nq * 32 + s * 8;
                unsigned b0 = f2tf32(Ws[cur][nb + gi][k0 + ti]);
                unsigned b1 = f2tf32(Ws[cur][nb + gi][k0 + ti + 4]);
                asm volatile(
                    "mma.sync.aligned.m16n8k8.row.col.f32.tf32.tf32.f32 "
                    "{%0,%1,%2,%3}, {%4,%5,%6,%7}, {%8,%9}, {%0,%1,%2,%3};\n"
                    : "+f"(d[s][0]), "+f"(d[s][1]), "+f"(d[s][2]), "+f"(d[s][3])
                    : "r"(a0), "r"(a1), "r"(a2), "r"(a3), "r"(b0), "r"(b1));
            }
        }
    }

    float* p = P + (size_t)blockIdx.y * 32 * N;
    #pragma unroll
    for (int s = 0; s < 4; s++) {
        const int col = n0 + nq * 32 + s * 8 + ti * 2;
        *(float2*)&p[r0 * N + col] = make_float2(d[s][0], d[s][1]);
        *(float2*)&p[(r0 + 8) * N + col] = make_float2(d[s][2], d[s][3]);
    }
}

// reduce split-K partials for the O projection into d_out
__global__ void reduce_out(float* __restrict__ out, int total4) {
    int i = blockIdx.x * blockDim.x + threadIdx.x;
    if (i >= total4) return;
    float4 r = make_float4(0.f, 0.f, 0.f, 0.f);
    #pragma unroll
    for (int s = 0; s < SPLITK; s++) {
        float4 x = *(const float4*)&g_part[(size_t)s * (B_ * H_) + i * 4];
        r.x += x.x; r.y += x.y; r.z += x.z; r.w += x.w;
    }
    ((float4*)out)[i] = r;
}

// ============================================================
// split-K reduce + RMSNorm + RoPE (tables) + k,v scatter.
// ============================================================
__global__ void norm_rope_scatter(const float* __restrict__ q_norm_w,
                                  const float* __restrict__ k_norm_w,
                                  const int* __restrict__ out_cache_loc,
                                  float* __restrict__ k_buf,
                                  float* __restrict__ v_buf) {
    const int head = blockIdx.x;
    const int b = blockIdx.y;
    const int tid = threadIdx.x;
    const int off = b * QKVN + head * D_ + tid;

    float x = 0.f;
    #pragma unroll
    for (int s = 0; s < SPLITK; s++) x += g_part[(size_t)s * (B_ * QKVN) + off];

    if (head >= NH_ + NKV_) {
        int h = head - (NH_ + NKV_);
        int loc = out_cache_loc[b];
        v_buf[(((size_t)b * KV_ + loc) * NKV_ + h) * D_ + tid] = x;
        return;
    }

    __shared__ float sred[4];
    float ss = x * x;
    #pragma unroll
    for (int o = 16; o; o >>= 1) ss += __shfl_xor_sync(0xffffffffu, ss, o);
    if ((tid & 31) == 0) sred[tid >> 5] = ss;
    __syncthreads();
    float total = sred[0] + sred[1] + sred[2] + sred[3];
    float rms = rsqrtf(total * (1.0f / D_) + 1e-6f);
    const float* wn = (head < NH_) ? q_norm_w : k_norm_w;
    float y = x * rms * wn[tid];

    __shared__ float ys[128];
    ys[tid] = y;
    __syncthreads();
    int i = tid & 63;
    float c = g_cosb[b][i], s = g_sinb[b][i];
    float outv = (tid < 64) ? (ys[tid] * c - ys[tid + 64] * s)
                            : (ys[tid] * c + ys[tid - 64] * s);

    if (head < NH_) {
        g_qkv[off] = outv;
    } else {
        int h = head - NH_;
        int loc = out_cache_loc[b];
        k_buf[(((size_t)b * KV_ + loc) * NKV_ + h) * D_ + tid] = outv;
    }
}

// ============================================================
// Fused flash-decode chunk (best-measured form — unchanged).
// ============================================================
__global__ __launch_bounds__(256, 6) void attn_chunk_kernel(
        const float* __restrict__ k_buf, const float* __restrict__ v_buf) {
    const int chunk = blockIdx.x, h = blockIdx.y, b = blockIdx.z;
    const int tid = threadIdx.x;
    const int warp = tid >> 5, lane = tid & 31;

    __shared__ float sbuf[4 * G_ * 64 * 2];
    float (*sc)[CS] = (float(*)[CS])sbuf;
    __shared__ float wred[G_][8];
    __shared__ float gm[G_], gs[G_];

    float4 q4[G_];
    #pragma unroll
    for (int g = 0; g < G_; g++)
        q4[g] = *(const float4*)&g_qkv[b * QKVN + (h * G_ + g) * D_ + lane * 4];

    const int s0 = chunk * CS;
    #pragma unroll 4
    for (int i = warp; i < CS; i += 8) {
        float4 kv = *(const float4*)&k_buf[(((size_t)b * KV_ + s0 + i) * NKV_ + h) * D_ + lane * 4];
        float p[G_];
        #pragma unroll
        for (int g = 0; g < G_; g++)
            p[g] = q4[g].x * kv.x + q4[g].y * kv.y + q4[g].z * kv.z + q4[g].w * kv.w;
        #pragma unroll
        for (int g = 0; g < G_; g++)
            #pragma unroll
            for (int o = 16; o; o >>= 1) p[g] += __shfl_xor_sync(0xffffffffu, p[g], o);
        if (lane == 0) {
            #pragma unroll
            for (int g = 0; g < G_; g++) sc[g][i] = p[g] * SCALE_;
        }
    }
    __syncthreads();

    {
        const int g = tid >> 6;
        const int j = tid & 63;
        float m = -1e30f;
        #pragma unroll
        for (int e = 0; e < CS / 64; e++) m = fmaxf(m, sc[g][j + e * 64]);
        #pragma unroll
        for (int o = 16; o; o >>= 1) m = fmaxf(m, __shfl_xor_sync(0xffffffffu, m, o));
        if (lane == 0) wred[g][warp & 1] = m;
        __syncthreads();
        m = fmaxf(wred[g][0], wred[g][1]);

        float sum = 0.f;
        #pragma unroll
        for (int e = 0; e < CS / 64; e++) {
            float ex = __expf(sc[g][j + e * 64] - m);
            sc[g][j + e * 64] = ex;
            sum += ex;
        }
        #pragma unroll
        for (int o = 16; o; o >>= 1) sum += __shfl_xor_sync(0xffffffffu, sum, o);
        if (lane == 0) wred[g][2 + (warp & 1)] = sum;
        __syncthreads();
        if (j == 0) { gm[g] = m; gs[g] = wred[g][2] + wred[g][3]; }
    }
    __syncthreads();

    const int d2 = tid & 63;
    const int q = tid >> 6;
    float2 acc[G_];
    #pragma unroll
    for (int g = 0; g < G_; g++) acc[g] = make_float2(0.f, 0.f);

    const float* vp = &v_buf[(((size_t)b * KV_ + s0 + q * 64) * NKV_ + h) * D_ + d2 * 2];
    #pragma unroll 8
    for (int sl = 0; sl < 64; sl++) {
        float2 v = *(const float2*)(vp + (size_t)sl * (NKV_ * D_));
        #pragma unroll
        for (int g = 0; g < G_; g++) {
            float p = sc[g][q * 64 + sl];
            acc[g].x += p * v.x;
            acc[g].y += p * v.y;
        }
    }
    __syncthreads();

    float2 (*psh)[G_][64] = (float2(*)[G_][64])sbuf;
    #pragma unroll
    for (int g = 0; g < G_; g++) psh[q][g][d2] = acc[g];
    __syncthreads();

    if (q == 0) {
        const size_t obase = ((((size_t)chunk * B_ + b) * NKV_ + h) * G_) * D_;
        #pragma unroll
        for (int g = 0; g < G_; g++) {
            float2 r0 = psh[0][g][d2], r1 = psh[1][g][d2];
            float2 r2 = psh[2][g][d2], r3 = psh[3][g][d2];
            float2 r = make_float2(r0.x + r1.x + r2.x + r3.x,
                                   r0.y + r1.y + r2.y + r3.y);
            *(float2*)&g_opart[obase + g * D_ + d2 * 2] = r;
        }
        if (d2 < G_) {
            size_t msb = ((((size_t)chunk * B_ + b) * NKV_ + h) * G_ + d2) * 2;
            g_ms[msb] = gm[d2];
            g_ms[msb + 1] = gs[d2];
        }
    }
}

// ============================================================
// Combine chunk partials: grid (NH=32, b=32), 128 threads.
// ============================================================
__global__ void attn_combine_kernel() {
    const int head = blockIdx.x;
    const int b = blockIdx.y;
    const int h = head >> 2, g = head & 3;
    const int d = threadIdx.x;

    float M = -1e30f;
    float mloc[NCHUNK];
    #pragma unroll
    for (int c = 0; c < NCHUNK; c++) {
        size_t msb = ((((size_t)c * B_ + b) * NKV_ + h) * G_ + g) * 2;
        mloc[c] = g_ms[msb];
        M = fmaxf(M, mloc[c]);
    }
    float S = 0.f, o = 0.f;
    #pragma unroll
    for (int c = 0; c < NCHUNK; c++) {
        size_t msb = ((((size_t)c * B_ + b) * NKV_ + h) * G_ + g) * 2;
        float w = __expf(mloc[c] - M);
        S += g_ms[msb + 1] * w;
        o += g_opart[(((((size_t)c * B_ + b) * NKV_ + h) * G_ + g)) * D_ + d] * w;
    }
    g_o[b * (NH_ * D_) + head * D_ + d] = o / S;
}

// ============================================================
extern "C" void kernel_launch(void* const* d_in, const int* in_sizes, int n_in,
                              void* d_out, int out_size) {
    const int*   position_ids  = (const int*)  d_in[0];
    const float* hidden_states = (const float*)d_in[1];
    float*       k_buffer      = (float*)      d_in[2];
    float*       v_buffer      = (float*)      d_in[3];
    const int*   out_cache_loc = (const int*)  d_in[4];
    const float* wqkv          = (const float*)d_in[5];
    const float* wo            = (const float*)d_in[6];
    const float* q_norm_w      = (const float*)d_in[7];
    const float* k_norm_w      = (const float*)d_in[8];
    float* out = (float*)d_out;

    float* part_ptr; cudaGetSymbolAddress((void**)&part_ptr, g_part);
    float* o_ptr;    cudaGetSymbolAddress((void**)&o_ptr, g_o);

    // 1. RoPE tables
    rope_tables_kernel<<<B_, 64>>>(position_ids);
    // 2. QKV projection (tf32 MMA, 3-stage cp.async)
    gemm_splitk<<<dim3(QKVN / 128, SPLITK), 256>>>(hidden_states, wqkv, part_ptr, QKVN, H_);
    // 3. reduce + RMSNorm + RoPE + k,v scatter
    norm_rope_scatter<<<dim3(NH_ + 2 * NKV_, B_), 128>>>(
        q_norm_w, k_norm_w, out_cache_loc, k_buffer, v_buffer);
    // 4. fused flash-decode
    attn_chunk_kernel<<<dim3(NCHUNK, NKV_, B_), 256>>>(k_buffer, v_buffer);
    // 5. combine partials
    attn_combine_kernel<<<dim3(NH_, B_), 128>>>();
    // 6. O projection + 7. reduce
    gemm_splitk<<<dim3(H_ / 128, SPLITK), 256>>>(o_ptr, wo, part_ptr, H_, H_);
    reduce_out<<<(B_ * H_ / 4 + 255) / 256, 256>>>(out, B_ * H_ / 4);
}